// round 16
// baseline (speedup 1.0000x reference)
#include <cuda_runtime.h>
#include <math.h>

// Problem constants
#define NSEQ   128          // 2*BATCH sequences
#define TLEN   64           // frames per sequence
#define DIMS   13           // feature dim
#define NPAIRS 8128         // NSEQ*(NSEQ-1)/2, pairs with a<b (diag is masked to 0)
#define WPB    2            // warps per block; 8128/2 = 4064 full blocks (no remainder!)

typedef unsigned long long u64;

static __device__ float g_R[NSEQ * NSEQ];          // raw soft-DTW values (diag never touched)
static __device__ unsigned int g_done = 0;         // completion counter (last block resets)

__device__ __forceinline__ float ex2f(float x) {
    float r; asm("ex2.approx.ftz.f32 %0, %1;" : "=f"(r) : "f"(x)); return r;
}
__device__ __forceinline__ float lg2f(float x) {
    float r; asm("lg2.approx.ftz.f32 %0, %1;" : "=f"(r) : "f"(x)); return r;
}
__device__ __forceinline__ u64 fmul2(u64 a, u64 b) {
    u64 d; asm("mul.rn.f32x2 %0, %1, %2;" : "=l"(d) : "l"(a), "l"(b)); return d;
}
__device__ __forceinline__ u64 ffma2(u64 a, u64 b, u64 c) {
    u64 d; asm("fma.rn.f32x2 %0, %1, %2, %3;" : "=l"(d) : "l"(a), "l"(b), "l"(c)); return d;
}
__device__ __forceinline__ float pairsum(u64 v) {
    float lo, hi;
    asm("mov.b64 {%0, %1}, %2;" : "=f"(lo), "=f"(hi) : "l"(v));
    return lo + hi;
}
__device__ __forceinline__ u64 pack2(float lo, float hi) {
    u64 r; asm("mov.b64 %0, {%1, %2};" : "=l"(r) : "f"(lo), "f"(hi)); return r;
}

// Raw frame pointer: sequence n (0..127), frame t (0..63)
__device__ __forceinline__ const float* frame_ptr(
    const float* __restrict__ xxx, const float* __restrict__ yyy, int n, int t) {
    return (n < 64) ? (xxx + ((size_t)n * TLEN + t) * DIMS)
                    : (yyy + ((size_t)(n - 64) * TLEN + t) * DIMS);
}

// ---------------------------------------------------------------------------
// Fused padding (computed on the fly, no prep kernel):
//   A-regs: slots [0..12]=-2x, [13]=-2|x|^2, [14]=1,     [15]=0
//   B-smem: slots [0..12]=x,   [13]=-0.5,    [14]=|x|^2, [15]=0
// => dot16(A,B) = -2*dot13 + |xa|^2 + |xb|^2 = D exactly.
// ---------------------------------------------------------------------------

#define SOFTMIN_CELL(up, left, diag, dcur, validExpr, rnew)                    \
    {                                                                          \
        const float m1_ = fminf(up, left);                                     \
        const float M1_ = fmaxf(up, left);                                     \
        const float mm_ = fminf(m1_, diag);                                    \
        const float xx_ = fmaxf(m1_, diag);                                    \
        const float mk_ = mm_ * KK;                                            \
        const float e1_ = ex2f(fmaf(-KK, xx_, mk_));                           \
        const float e2_ = ex2f(fmaf(-KK, M1_, mk_));                           \
        const float sm_ = fmaf(-GL2, lg2f(1.0f + e1_ + e2_), mm_);             \
        rnew = (validExpr) ? (dcur + sm_) : INFV;                              \
    }

// D = dot16(A'_row, xb[k]) via 8 packed f32x2 FMAs + horizontal add
#define PROD_D(bp, Aa, Ab, Ac, Ad, dOut)                                       \
    {                                                                          \
        const ulonglong2 Ba_ = (bp)[0];                                        \
        const ulonglong2 Bb_ = (bp)[1];                                        \
        const ulonglong2 Bc_ = (bp)[2];                                        \
        const ulonglong2 Bd_ = (bp)[3];                                        \
        u64 acc_ = fmul2(Aa.x, Ba_.x);                                         \
        acc_ = ffma2(Aa.y, Ba_.y, acc_);                                       \
        acc_ = ffma2(Ab.x, Bb_.x, acc_);                                       \
        acc_ = ffma2(Ab.y, Bb_.y, acc_);                                       \
        acc_ = ffma2(Ac.x, Bc_.x, acc_);                                       \
        acc_ = ffma2(Ac.y, Bc_.y, acc_);                                       \
        acc_ = ffma2(Ad.x, Bd_.x, acc_);                                       \
        acc_ = ffma2(Ad.y, Bd_.y, acc_);                                       \
        dOut = pairsum(acc_);                                                  \
    }

// One 32-row strip of the DP. S is a compile-time constant (0 or 1).
// A row built from RAW input (13 loads + norm + pack) — replaces prep.
template <int S>
__device__ __forceinline__ float dp_strip(
    int L, int Lq, int a,
    const float* __restrict__ xxx, const float* __restrict__ yyy,
    const float* __restrict__ s_xb,   // this warp's xb tile (B-padded)
    float* __restrict__ s_ring,       // this warp's 32x32 D ring
    float* __restrict__ s_rowbuf)     // this warp's boundary row
{
    const float INFV = 1e10f;
    const float KK   = 14.4269504088896341f;   // log2(e)/gamma, gamma = 0.1
    const float GL2  = 0.069314718055994531f;  // gamma * ln(2)

    const int row = S * 32 + L;
    // Build A-packed registers from raw input
    const float* pa = frame_ptr(xxx, yyy, a, row);
    float x[13];
    float s = 0.f;
#pragma unroll
    for (int d = 0; d < DIMS; ++d) { x[d] = pa[d]; s = fmaf(x[d], x[d], s); }
    ulonglong2 Aa, Ab, Ac, Ad;
    Aa.x = pack2(-2.f * x[0],  -2.f * x[1]);
    Aa.y = pack2(-2.f * x[2],  -2.f * x[3]);
    Ab.x = pack2(-2.f * x[4],  -2.f * x[5]);
    Ab.y = pack2(-2.f * x[6],  -2.f * x[7]);
    Ac.x = pack2(-2.f * x[8],  -2.f * x[9]);
    Ac.y = pack2(-2.f * x[10], -2.f * x[11]);
    Ad.x = pack2(-2.f * x[12], -2.f * s);
    Ad.y = pack2(1.0f, 0.0f);

    float r1 = INFV;
    // diag carry: holds previous step's (post-override) up. First use at k=0
    // is cell (row, -L): only lane 0 / strip 0 needs corner R(-1,-1)=0 there.
    float dg = (S == 0 && L == 0) ? 0.0f : INFV;

    // ---------------- Phase A: k = 0..63 (produce D column + consume) -------
#pragma unroll 4
    for (int k = 0; k < TLEN; ++k) {
        // produce D[row][k]
        float dnew;
        {
            const ulonglong2* bp = (const ulonglong2*)&s_xb[k * 16];
            PROD_D(bp, Aa, Ab, Ac, Ad, dnew);
            s_ring[(k & 31) * 32 + L] = dnew;   // bank = L, conflict-free
        }

        // consume cell (row, j = k-L). Lane 0 reads a one-back slot (Lq=1)
        // and takes dnew from register: no same-step same-address LDS
        // (B300 smem has no store-forwarding).
        const float dld = s_ring[((k - Lq) & 31) * 32 + L];
        const float dcur = (L == 0) ? dnew : dld;
        float up = __shfl_up_sync(0xffffffffu, r1, 1);
        if (L == 0) up = (S == 0) ? INFV : s_rowbuf[k];   // R[31][j], j==k
        const float left = r1;

        float rnew;
        SOFTMIN_CELL(up, left, dg, dcur, k >= L, rnew);
        if (S == 0 && L == 31 && k >= L) s_rowbuf[k - L] = rnew;
        dg = up;       // diag for next step
        r1 = rnew;
    }

    // ---------------- Phase B: k = 64..94 (drain; j = k-L in [33,63]) -------
    // Lane 0 is invalid throughout phase B; no up override needed — its
    // results are discarded by the validity SEL and feed nothing live.
#pragma unroll 4
    for (int k = TLEN; k < TLEN + 31; ++k) {
        const float dcur = s_ring[((k - Lq) & 31) * 32 + L];
        const float up = __shfl_up_sync(0xffffffffu, r1, 1);
        const float left = r1;

        float rnew;
        SOFTMIN_CELL(up, left, dg, dcur, k < L + TLEN, rnew);
        if (S == 0 && L == 31) s_rowbuf[k - 31] = rnew;   // j in [33,63]
        dg = up;
        r1 = rnew;
    }
    return r1;
}

// ---------------------------------------------------------------------------
// THE kernel: prep (fused staging) + soft-DTW pairs + tail loss reduction.
// One warp per (a<b) pair; the LAST block to finish (atomic counter) computes
// the contrastive loss from g_R with deterministic fixed-order reductions.
// ---------------------------------------------------------------------------
__global__ void __launch_bounds__(WPB * 32, 12) pairs_kernel(
    const float* __restrict__ xxx, const float* __restrict__ yyy,
    float* __restrict__ out)
{
    __shared__ __align__(16) float s_xb[WPB][TLEN * 16];  // 8 KB: xb frames (B-padded)
    __shared__ float s_ring[WPB][32 * 32];                // 8 KB: D-column ring
    __shared__ float s_rowbuf[WPB][TLEN];                 // .5 KB: strip boundary row
    __shared__ unsigned int s_last;
    __shared__ float s_acc[WPB];

    const int w = threadIdx.x >> 5;
    const int L = threadIdx.x & 31;
    const int Lq = L + (L == 0);    // ring read delay (lane 0 biased one back)
    const int idx = blockIdx.x * WPB + w;   // always < NPAIRS (4064*2 = 8128)

    // --- decode triangular pair index: off(a) = a*(255-a)/2 ---
    int a = (int)((255.0f - sqrtf(fmaxf(0.f, 65025.0f - 8.0f * (float)idx))) * 0.5f);
    if (a < 0) a = 0;
    if (a > 126) a = 126;
    while (a > 0 && (a * (255 - a)) / 2 > idx) --a;
    while (((a + 1) * (254 - a)) / 2 <= idx) ++a;
    const int b = a + 1 + (idx - (a * (255 - a)) / 2);

    // --- stage xb from RAW input (B-padding; 2 frames per lane) ---
#pragma unroll
    for (int q = 0; q < 2; ++q) {
        const int t = q * 32 + L;
        const float* pb = frame_ptr(xxx, yyy, b, t);
        float* dst = &s_xb[w][t * 16];
        float s = 0.f;
#pragma unroll
        for (int d = 0; d < DIMS; ++d) {
            const float v = pb[d];
            s = fmaf(v, v, s);
            dst[d] = v;
        }
        dst[13] = -0.5f;
        dst[14] = s;
        dst[15] = 0.f;
    }
    __syncwarp();

    dp_strip<0>(L, Lq, a, xxx, yyy, s_xb[w], s_ring[w], s_rowbuf[w]);
    __syncwarp();   // strip 0's rowbuf writes -> strip 1's lane-0 reads
    const float Rv = dp_strip<1>(L, Lq, a, xxx, yyy, s_xb[w], s_ring[w], s_rowbuf[w]);

    if (L == 31) {
        g_R[a * NSEQ + b] = Rv;         // R[63][63]
        g_R[b * NSEQ + a] = Rv;         // sim is symmetric
    }
    __threadfence();    // publish this block's g_R writes before the atomic
    __syncthreads();

    if (threadIdx.x == 0) {
        const unsigned int old = atomicAdd(&g_done, 1u);
        s_last = (old == gridDim.x - 1) ? 1u : 0u;
    }
    __syncthreads();

    if (s_last) {
        // Last block: all other blocks' g_R writes are published (each did
        // threadfence before its atomic). Reset counter for the next replay.
        if (threadIdx.x == 0) g_done = 0;
        __threadfence();    // acquire side: order g_R reads after counter obs

        // Contrastive loss: sim = R/ENERGY, zero diag.
        // Warp w handles rows [w*64, w*64+64). Deterministic fixed order.
        const float INV_E = 2.0f;                 // 1/ENERGY
        const float L2E   = 1.4426950408889634f;  // log2(e)
        const float LN2   = 0.6931471805599453f;

        float acc = 0.f;
#pragma unroll 4
        for (int i = 0; i < 64; ++i) {
            const int r = w * 64 + i;
            float v0 = (L == r)       ? 0.0f : g_R[r * NSEQ + L]       * INV_E;
            float v1 = (L + 32 == r)  ? 0.0f : g_R[r * NSEQ + L + 32]  * INV_E;
            float v2 = (L + 64 == r)  ? 0.0f : g_R[r * NSEQ + L + 64]  * INV_E;
            float v3 = (L + 96 == r)  ? 0.0f : g_R[r * NSEQ + L + 96]  * INV_E;

            float mx = fmaxf(fmaxf(v0, v1), fmaxf(v2, v3));
#pragma unroll
            for (int o = 16; o > 0; o >>= 1)
                mx = fmaxf(mx, __shfl_xor_sync(0xffffffffu, mx, o));

            float sum = ex2f((v0 - mx) * L2E) + ex2f((v1 - mx) * L2E)
                      + ex2f((v2 - mx) * L2E) + ex2f((v3 - mx) * L2E);
#pragma unroll
            for (int o = 16; o > 0; o >>= 1)
                sum += __shfl_xor_sync(0xffffffffu, sum, o);

            const float lse = fmaf(LN2, lg2f(sum), mx);
            const float pos = g_R[r * NSEQ + ((r + 64) & 127)] * INV_E;
            acc += lse - pos;   // identical in all lanes after butterflies
        }
        if (L == 0) s_acc[w] = acc;
        __syncthreads();
        if (threadIdx.x == 0)
            out[0] = (s_acc[0] + s_acc[1]) * (1.0f / 128.0f);
    }
}

// ---------------------------------------------------------------------------
extern "C" void kernel_launch(void* const* d_in, const int* in_sizes, int n_in,
                              void* d_out, int out_size) {
    const float* xxx = (const float*)d_in[0];
    const float* yyy = (const float*)d_in[1];
    float* out = (float*)d_out;

    pairs_kernel<<<NPAIRS / WPB, WPB * 32>>>(xxx, yyy, out);
}